// round 7
// baseline (speedup 1.0000x reference)
#include <cuda_runtime.h>

#define NN 8192
#define DIN 512
#define DOUT 64
#define HEADS 8
#define MWORDS 256
#define L2E 1.44269504088896f

__device__ float    g_Wh[NN * 512];         // [j][h*64+d], tf32-rounded
__device__ float    g_WhT[HEADS * 64 * NN]; // [h][d][j-permuted], tf32-rounded
__device__ float    g_f1[HEADS * NN];       // * log2e (from unrounded Wh)
__device__ float    g_f2[HEADS * NN];       // * log2e
__device__ float    g_f2P[HEADS * NN];      // * log2e, j-permuted per 8
__device__ float    g_f2max[HEADS];
__device__ unsigned g_mask[NN * MWORDS];

// ---------------- helpers ----------------
__device__ __forceinline__ unsigned long long fma2(unsigned long long a,
                                                   unsigned long long b,
                                                   unsigned long long c) {
    unsigned long long d;
    asm("fma.rn.f32x2 %0, %1, %2, %3;" : "=l"(d) : "l"(a), "l"(b), "l"(c));
    return d;
}
__device__ __forceinline__ unsigned long long pack2(float x) {
    unsigned long long d;
    asm("mov.b64 %0, {%1, %1};" : "=l"(d) : "f"(x));
    return d;
}
__device__ __forceinline__ float2 unpack2(unsigned long long v) {
    float2 f;
    asm("mov.b64 {%0, %1}, %2;" : "=f"(f.x), "=f"(f.y) : "l"(v));
    return f;
}
__device__ __forceinline__ unsigned tf32r(float x) {
    unsigned r;
    asm("cvt.rna.tf32.f32 %0, %1;" : "=r"(r) : "f"(x));
    return r;
}
__device__ __forceinline__ float ex2f(float x) {
    float r;
    asm("ex2.approx.f32 %0, %1;" : "=f"(r) : "f"(x));
    return r;
}
__device__ __forceinline__ void mma_tf32(float c[4], unsigned a0, unsigned a1,
                                         unsigned a2, unsigned a3,
                                         unsigned b0, unsigned b1) {
    asm volatile(
        "mma.sync.aligned.m16n8k8.row.col.f32.tf32.tf32.f32 "
        "{%0,%1,%2,%3}, {%4,%5,%6,%7}, {%8,%9}, {%0,%1,%2,%3};"
        : "+f"(c[0]), "+f"(c[1]), "+f"(c[2]), "+f"(c[3])
        : "r"(a0), "r"(a1), "r"(a2), "r"(a3), "r"(b0), "r"(b1));
}
__device__ __forceinline__ void cp16(void* dst, const void* src) {
    unsigned d = (unsigned)__cvta_generic_to_shared(dst);
    asm volatile("cp.async.cg.shared.global [%0], [%1], 16;" :: "r"(d), "l"(src));
}
__device__ __forceinline__ void cp8(void* dst, const void* src) {
    unsigned d = (unsigned)__cvta_generic_to_shared(dst);
    asm volatile("cp.async.ca.shared.global [%0], [%1], 8;" :: "r"(d), "l"(src));
}
__device__ __forceinline__ void cp_commit() { asm volatile("cp.async.commit_group;"); }
__device__ __forceinline__ void cp_wait1()  { asm volatile("cp.async.wait_group 1;"); }

// ---------------- kernel 1: adj -> bitmask ----------------
__global__ __launch_bounds__(256) void mask_kernel(const int* __restrict__ adj) {
    const int UN = 8;
    long long w0 = ((long long)blockIdx.x * 8 + (threadIdx.x >> 5)) * UN;
    int lane = threadIdx.x & 31;
    int v[UN];
#pragma unroll
    for (int u = 0; u < UN; ++u) v[u] = adj[(w0 + u) * 32 + lane];
#pragma unroll
    for (int u = 0; u < UN; ++u) {
        unsigned b = __ballot_sync(0xffffffffu, v[u] > 0);
        if (lane == 0) g_mask[w0 + u] = b;
    }
}

// ---------------- kernel 2: Wh = x @ W (+ f1/f2 from UNROUNDED) -------------
__global__ __launch_bounds__(256, 2) void gemm_wh_kernel(
    const float* __restrict__ x, const float* __restrict__ W,
    const float* __restrict__ a1, const float* __restrict__ a2)
{
    __shared__ float As[16 * 128];
    __shared__ float Bs[16 * 64];
    const int h = blockIdx.y, row0 = blockIdx.x * 128, t = threadIdx.x;
    const int dg = t & 7, rg = t >> 3;
    const float* Wb = W + h * (DIN * DOUT);

    unsigned long long acc[4][4];
#pragma unroll
    for (int r = 0; r < 4; ++r)
#pragma unroll
        for (int q = 0; q < 4; ++q) acc[r][q] = 0ull;

    for (int kt = 0; kt < 32; ++kt) {
        __syncthreads();
#pragma unroll
        for (int s2 = 0; s2 < 2; ++s2) {
            int idx = t + s2 * 256;
            int row = idx >> 2, kq = idx & 3;
            float4 v = ((const float4*)x)[(long long)(row0 + row) * 128 + kt * 4 + kq];
            As[(kq * 4 + 0) * 128 + row] = v.x;
            As[(kq * 4 + 1) * 128 + row] = v.y;
            As[(kq * 4 + 2) * 128 + row] = v.z;
            As[(kq * 4 + 3) * 128 + row] = v.w;
        }
        {
            int k = t >> 4, dq = t & 15;
            ((float4*)Bs)[k * 16 + dq] = ((const float4*)Wb)[(kt * 16 + k) * 16 + dq];
        }
        __syncthreads();
#pragma unroll
        for (int k = 0; k < 16; ++k) {
            float4 av = *(const float4*)&As[k * 128 + rg * 4];
            const unsigned long long* bp =
                (const unsigned long long*)&Bs[k * 64 + dg * 8];
            unsigned long long b0 = bp[0], b1 = bp[1], b2 = bp[2], b3 = bp[3];
            unsigned long long p;
            p = pack2(av.x);
            acc[0][0] = fma2(p, b0, acc[0][0]); acc[0][1] = fma2(p, b1, acc[0][1]);
            acc[0][2] = fma2(p, b2, acc[0][2]); acc[0][3] = fma2(p, b3, acc[0][3]);
            p = pack2(av.y);
            acc[1][0] = fma2(p, b0, acc[1][0]); acc[1][1] = fma2(p, b1, acc[1][1]);
            acc[1][2] = fma2(p, b2, acc[1][2]); acc[1][3] = fma2(p, b3, acc[1][3]);
            p = pack2(av.z);
            acc[2][0] = fma2(p, b0, acc[2][0]); acc[2][1] = fma2(p, b1, acc[2][1]);
            acc[2][2] = fma2(p, b2, acc[2][2]); acc[2][3] = fma2(p, b3, acc[2][3]);
            p = pack2(av.w);
            acc[3][0] = fma2(p, b0, acc[3][0]); acc[3][1] = fma2(p, b1, acc[3][1]);
            acc[3][2] = fma2(p, b2, acc[3][2]); acc[3][3] = fma2(p, b3, acc[3][3]);
        }
    }

    float a1r[8], a2r[8];
#pragma unroll
    for (int q = 0; q < 8; ++q) {
        a1r[q] = a1[h * 64 + dg * 8 + q];
        a2r[q] = a2[h * 64 + dg * 8 + q];
    }
#pragma unroll
    for (int r = 0; r < 4; ++r) {
        int gi = row0 + rg * 4 + r;
        float vals[8], vr[8];
#pragma unroll
        for (int q = 0; q < 4; ++q) {
            float2 f = unpack2(acc[r][q]);
            vals[2 * q] = f.x; vals[2 * q + 1] = f.y;
            vr[2 * q]     = __uint_as_float(tf32r(f.x));
            vr[2 * q + 1] = __uint_as_float(tf32r(f.y));
        }
        float4 o0 = make_float4(vr[0], vr[1], vr[2], vr[3]);
        float4 o1 = make_float4(vr[4], vr[5], vr[6], vr[7]);
        ((float4*)g_Wh)[(long long)gi * 128 + h * 16 + dg * 2]     = o0;
        ((float4*)g_Wh)[(long long)gi * 128 + h * 16 + dg * 2 + 1] = o1;
        float s1 = 0.f, s2v = 0.f;
#pragma unroll
        for (int q = 0; q < 8; ++q) { s1 += vals[q] * a1r[q]; s2v += vals[q] * a2r[q]; }
#pragma unroll
        for (int d = 4; d; d >>= 1) {
            s1  += __shfl_down_sync(0xffffffffu, s1,  d, 8);
            s2v += __shfl_down_sync(0xffffffffu, s2v, d, 8);
        }
        if (dg == 0) {
            g_f1[h * NN + gi] = s1 * L2E;
            g_f2[h * NN + gi] = s2v * L2E;
        }
    }
}

// ---------------- kernel 2b: per-head max of f2 ----------------
__global__ __launch_bounds__(256) void f2max_kernel() {
    __shared__ float red[8];
    int h = blockIdx.x;
    float m = -3.4e38f;
    for (int i = threadIdx.x; i < NN; i += 256)
        m = fmaxf(m, g_f2[h * NN + i]);
#pragma unroll
    for (int s = 16; s; s >>= 1)
        m = fmaxf(m, __shfl_xor_sync(0xffffffffu, m, s));
    if ((threadIdx.x & 31) == 0) red[threadIdx.x >> 5] = m;
    __syncthreads();
    if (threadIdx.x < 8) {
        m = red[threadIdx.x];
#pragma unroll
        for (int s = 4; s; s >>= 1)
            m = fmaxf(m, __shfl_xor_sync(0x000000ffu, m, s));
        if (threadIdx.x == 0) g_f2max[h] = m;
    }
}

// ---------------- kernel 2c: transpose Wh -> [h][d][j'], permute f2 --------
// within-8 perm p(j): (a2 a1 a0) -> (a1 a0 a2); inverse: (b2 b1 b0) -> (b0 b2 b1)
__global__ __launch_bounds__(256) void transpose_kernel() {
    __shared__ float sh[64 * 72];
    const int jt = blockIdx.x, h = blockIdx.y, t = threadIdx.x;
    const long long j0 = (long long)jt * 64;
#pragma unroll
    for (int s = 0; s < 4; ++s) {
        int idx = t + s * 256;
        int j = idx >> 4, q = idx & 15;
        float4 v = ((const float4*)g_Wh)[(j0 + j) * 128 + h * 16 + q];
        sh[(q * 4 + 0) * 72 + j] = v.x;
        sh[(q * 4 + 1) * 72 + j] = v.y;
        sh[(q * 4 + 2) * 72 + j] = v.z;
        sh[(q * 4 + 3) * 72 + j] = v.w;
    }
    if (t < 64) {
        int jp = (t & ~7) | ((t & 3) << 1) | ((t >> 2) & 1);
        g_f2P[h * NN + j0 + jp] = g_f2[h * NN + j0 + t];
    }
    __syncthreads();
#pragma unroll
    for (int s = 0; s < 4; ++s) {
        int idx = t + s * 256;
        int d = idx >> 4, c = idx & 15;
        int jj = c * 4;
        float4 v;
        v.x = sh[d * 72 + ((jj & ~7) | (((jj + 0) & 1) << 2) | (((jj + 0) & 7) >> 1))];
        v.y = sh[d * 72 + ((jj & ~7) | (((jj + 1) & 1) << 2) | (((jj + 1) & 7) >> 1))];
        v.z = sh[d * 72 + ((jj & ~7) | (((jj + 2) & 1) << 2) | (((jj + 2) & 7) >> 1))];
        v.w = sh[d * 72 + ((jj & ~7) | (((jj + 3) & 1) << 2) | (((jj + 3) & 7) >> 1))];
        ((float4*)g_WhT)[(((long long)(h * 64 + d)) * NN + j0) / 4 + c] = v;
    }
}

// ---------------- kernel 3: attention (tf32 mma, 3 CTAs/SM) ----------------
__global__ __launch_bounds__(256, 3) void attn_kernel(float* __restrict__ out) {
    __shared__ __align__(16) float    WhS[2][64 * 72];
    __shared__ __align__(16) float2   f2s[2][32];
    __shared__ __align__(16) unsigned maskS[2][256];

    const int h = blockIdx.y, row0 = blockIdx.x * 128, t = threadIdx.x;
    const int lane = t & 31, warp = t >> 5, gid = lane >> 2, tig = lane & 3;
    const int r0 = warp * 16 + gid, r1 = r0 + 8;
    const long long gr0 = row0 + r0, gr1 = row0 + r1;

    const float f2m = g_f2max[h];
    const float f1a = g_f1[h * NN + gr0], f1b = g_f1[h * NN + gr1];
    const float ea = f1a + f2m, eb = f1b + f2m;
    const float m0 = fmaxf(ea, 0.2f * ea), m1 = fmaxf(eb, 0.2f * eb);
    const float f1m0 = f1a - m0, c10 = fmaf(0.2f, f1a, -m0);
    const float f1m1 = f1b - m1, c11 = fmaf(0.2f, f1b, -m1);
    float l0 = 0.f, l1 = 0.f;

    float acc[8][4];
#pragma unroll
    for (int nc = 0; nc < 8; ++nc)
#pragma unroll
        for (int q = 0; q < 4; ++q) acc[nc][q] = 0.f;

    const int sd = t >> 2, sc = t & 3;
#define STAGE(jt, b) do {                                                     \
        long long js = (long long)(jt) * 64;                                  \
        const float* srow = &g_WhT[((long long)(h * 64 + sd)) * NN + js];     \
        _Pragma("unroll")                                                     \
        for (int s = 0; s < 4; ++s) {                                         \
            int c = sc * 4 + s;                                               \
            cp16(&WhS[b][sd * 72 + c * 4], srow + c * 4);                     \
        }                                                                     \
        if (t < 128) cp8(&maskS[b][t * 2],                                    \
                         &g_mask[(long long)(row0 + t) * MWORDS + (jt) * 2]); \
        if (t < 16)  cp16(&f2s[b][t * 2], &g_f2P[h * NN + js + t * 4]);       \
    } while (0)

    STAGE(0, 0);
    cp_commit();

    for (int jt = 0; jt < 128; ++jt) {
        const int cur = jt & 1;
        if (jt + 1 < 128) STAGE(jt + 1, cur ^ 1);
        cp_commit();
        cp_wait1();
        __syncthreads();

        const unsigned mr0a = maskS[cur][r0 * 2], mr0b = maskS[cur][r0 * 2 + 1];
        const unsigned mr1a = maskS[cur][r1 * 2], mr1b = maskS[cur][r1 * 2 + 1];
        const float* whb = &WhS[cur][gid * 72 + tig * 2];

#pragma unroll
        for (int kc = 0; kc < 8; ++kc) {
            const float2 f2p = f2s[cur][kc * 4 + tig];
            float s0 = fmaxf(f1m0 + f2p.x, fmaf(0.2f, f2p.x, c10));
            float s1 = fmaxf(f1m1 + f2p.x, fmaf(0.2f, f2p.x, c11));
            float s2 = fmaxf(f1m0 + f2p.y, fmaf(0.2f, f2p.y, c10));
            float s3 = fmaxf(f1m1 + f2p.y, fmaf(0.2f, f2p.y, c11));
            const int k0 = kc * 8 + tig, b0 = k0 & 31, b1 = (k0 + 4) & 31;
            const unsigned w0 = (kc < 4) ? mr0a : mr0b;
            const unsigned w1 = (kc < 4) ? mr1a : mr1b;
            if (!((w0 >> b0) & 1u)) s0 = -3.0e38f;
            if (!((w1 >> b0) & 1u)) s1 = -3.0e38f;
            if (!((w0 >> b1) & 1u)) s2 = -3.0e38f;
            if (!((w1 >> b1) & 1u)) s3 = -3.0e38f;
            const unsigned a0 = tf32r(ex2f(s0)), a1 = tf32r(ex2f(s1));
            const unsigned a2 = tf32r(ex2f(s2)), a3 = tf32r(ex2f(s3));
            l0 += __uint_as_float(a0) + __uint_as_float(a2);
            l1 += __uint_as_float(a1) + __uint_as_float(a3);
#pragma unroll
            for (int nc = 0; nc < 8; ++nc) {
                const float2 bb = *(const float2*)(whb + nc * 576 + kc * 8);
                mma_tf32(acc[nc], a0, a1, a2, a3,
                         __float_as_uint(bb.x), __float_as_uint(bb.y));
            }
        }
        __syncthreads();
    }

    l0 += __shfl_xor_sync(0xffffffffu, l0, 1);
    l0 += __shfl_xor_sync(0xffffffffu, l0, 2);
    l1 += __shfl_xor_sync(0xffffffffu, l1, 1);
    l1 += __shfl_xor_sync(0xffffffffu, l1, 2);
    const float inv0 = 1.0f / l0, inv1 = 1.0f / l1;

#pragma unroll
    for (int nc = 0; nc < 8; ++nc) {
        const int col = h * 64 + nc * 8 + tig * 2;
        ((float2*)out)[(gr0 * 512 + col) >> 1] =
            make_float2(acc[nc][0] * inv0, acc[nc][1] * inv0);
        ((float2*)out)[(gr1 * 512 + col) >> 1] =
            make_float2(acc[nc][2] * inv1, acc[nc][3] * inv1);
    }
}

// ---------------- launch ----------------
extern "C" void kernel_launch(void* const* d_in, const int* in_sizes, int n_in,
                              void* d_out, int out_size) {
    const float* x   = (const float*)d_in[0];
    const int*   adj = (const int*)d_in[1];
    const float* W   = (const float*)d_in[2];
    const float* a1  = (const float*)d_in[3];
    const float* a2  = (const float*)d_in[4];
    float* out = (float*)d_out;

    mask_kernel<<<(NN * MWORDS) / 64, 256>>>(adj);
    gemm_wh_kernel<<<dim3(NN / 128, HEADS), 256>>>(x, W, a1, a2);
    f2max_kernel<<<HEADS, 256>>>();
    transpose_kernel<<<dim3(NN / 64, HEADS), 256>>>();
    attn_kernel<<<dim3(NN / 128, HEADS), 256>>>(out);
}

// round 8
// speedup vs baseline: 1.1577x; 1.1577x over previous
#include <cuda_runtime.h>

#define NN 8192
#define DIN 512
#define DOUT 64
#define HEADS 8
#define MWORDS 256
#define L2E 1.44269504088896f

__device__ float    g_Wh[NN * 512];         // [j][h*64+d], tf32-rounded
__device__ float    g_WhT[HEADS * 64 * NN]; // [h][d][j-permuted], tf32-rounded
__device__ float    g_f1[HEADS * NN];       // * log2e (from unrounded Wh)
__device__ float    g_f2[HEADS * NN];       // * log2e
__device__ float    g_f2P[HEADS * NN];      // * log2e, j-permuted per 8
__device__ float    g_f2max[HEADS];
__device__ unsigned g_mask[NN * MWORDS];

// ---------------- helpers ----------------
__device__ __forceinline__ unsigned long long fma2(unsigned long long a,
                                                   unsigned long long b,
                                                   unsigned long long c) {
    unsigned long long d;
    asm("fma.rn.f32x2 %0, %1, %2, %3;" : "=l"(d) : "l"(a), "l"(b), "l"(c));
    return d;
}
__device__ __forceinline__ unsigned long long pack2(float x) {
    unsigned long long d;
    asm("mov.b64 %0, {%1, %1};" : "=l"(d) : "f"(x));
    return d;
}
__device__ __forceinline__ float2 unpack2(unsigned long long v) {
    float2 f;
    asm("mov.b64 {%0, %1}, %2;" : "=f"(f.x), "=f"(f.y) : "l"(v));
    return f;
}
__device__ __forceinline__ unsigned tf32r(float x) {
    unsigned r;
    asm("cvt.rna.tf32.f32 %0, %1;" : "=r"(r) : "f"(x));
    return r;
}
__device__ __forceinline__ float ex2f(float x) {
    float r;
    asm("ex2.approx.f32 %0, %1;" : "=f"(r) : "f"(x));
    return r;
}
__device__ __forceinline__ void mma_tf32(float c[4], unsigned a0, unsigned a1,
                                         unsigned a2, unsigned a3,
                                         unsigned b0, unsigned b1) {
    asm volatile(
        "mma.sync.aligned.m16n8k8.row.col.f32.tf32.tf32.f32 "
        "{%0,%1,%2,%3}, {%4,%5,%6,%7}, {%8,%9}, {%0,%1,%2,%3};"
        : "+f"(c[0]), "+f"(c[1]), "+f"(c[2]), "+f"(c[3])
        : "r"(a0), "r"(a1), "r"(a2), "r"(a3), "r"(b0), "r"(b1));
}
__device__ __forceinline__ void cp16(void* dst, const void* src) {
    unsigned d = (unsigned)__cvta_generic_to_shared(dst);
    asm volatile("cp.async.cg.shared.global [%0], [%1], 16;" :: "r"(d), "l"(src));
}
__device__ __forceinline__ void cp8(void* dst, const void* src) {
    unsigned d = (unsigned)__cvta_generic_to_shared(dst);
    asm volatile("cp.async.ca.shared.global [%0], [%1], 8;" :: "r"(d), "l"(src));
}
__device__ __forceinline__ void cp_commit() { asm volatile("cp.async.commit_group;"); }
__device__ __forceinline__ void cp_wait1()  { asm volatile("cp.async.wait_group 1;"); }

// ---------------- kernel 1: adj -> bitmask ----------------
__global__ __launch_bounds__(256) void mask_kernel(const int* __restrict__ adj) {
    const int UN = 8;
    long long w0 = ((long long)blockIdx.x * 8 + (threadIdx.x >> 5)) * UN;
    int lane = threadIdx.x & 31;
    int v[UN];
#pragma unroll
    for (int u = 0; u < UN; ++u) v[u] = adj[(w0 + u) * 32 + lane];
#pragma unroll
    for (int u = 0; u < UN; ++u) {
        unsigned b = __ballot_sync(0xffffffffu, v[u] > 0);
        if (lane == 0) g_mask[w0 + u] = b;
    }
}

// ---------------- kernel 2: Wh = x @ W (+ f1/f2 from UNROUNDED) -------------
__global__ __launch_bounds__(256, 2) void gemm_wh_kernel(
    const float* __restrict__ x, const float* __restrict__ W,
    const float* __restrict__ a1, const float* __restrict__ a2)
{
    __shared__ float As[16 * 128];
    __shared__ float Bs[16 * 64];
    const int h = blockIdx.y, row0 = blockIdx.x * 128, t = threadIdx.x;
    const int dg = t & 7, rg = t >> 3;
    const float* Wb = W + h * (DIN * DOUT);

    unsigned long long acc[4][4];
#pragma unroll
    for (int r = 0; r < 4; ++r)
#pragma unroll
        for (int q = 0; q < 4; ++q) acc[r][q] = 0ull;

    for (int kt = 0; kt < 32; ++kt) {
        __syncthreads();
#pragma unroll
        for (int s2 = 0; s2 < 2; ++s2) {
            int idx = t + s2 * 256;
            int row = idx >> 2, kq = idx & 3;
            float4 v = ((const float4*)x)[(long long)(row0 + row) * 128 + kt * 4 + kq];
            As[(kq * 4 + 0) * 128 + row] = v.x;
            As[(kq * 4 + 1) * 128 + row] = v.y;
            As[(kq * 4 + 2) * 128 + row] = v.z;
            As[(kq * 4 + 3) * 128 + row] = v.w;
        }
        {
            int k = t >> 4, dq = t & 15;
            ((float4*)Bs)[k * 16 + dq] = ((const float4*)Wb)[(kt * 16 + k) * 16 + dq];
        }
        __syncthreads();
#pragma unroll
        for (int k = 0; k < 16; ++k) {
            float4 av = *(const float4*)&As[k * 128 + rg * 4];
            const unsigned long long* bp =
                (const unsigned long long*)&Bs[k * 64 + dg * 8];
            unsigned long long b0 = bp[0], b1 = bp[1], b2 = bp[2], b3 = bp[3];
            unsigned long long p;
            p = pack2(av.x);
            acc[0][0] = fma2(p, b0, acc[0][0]); acc[0][1] = fma2(p, b1, acc[0][1]);
            acc[0][2] = fma2(p, b2, acc[0][2]); acc[0][3] = fma2(p, b3, acc[0][3]);
            p = pack2(av.y);
            acc[1][0] = fma2(p, b0, acc[1][0]); acc[1][1] = fma2(p, b1, acc[1][1]);
            acc[1][2] = fma2(p, b2, acc[1][2]); acc[1][3] = fma2(p, b3, acc[1][3]);
            p = pack2(av.z);
            acc[2][0] = fma2(p, b0, acc[2][0]); acc[2][1] = fma2(p, b1, acc[2][1]);
            acc[2][2] = fma2(p, b2, acc[2][2]); acc[2][3] = fma2(p, b3, acc[2][3]);
            p = pack2(av.w);
            acc[3][0] = fma2(p, b0, acc[3][0]); acc[3][1] = fma2(p, b1, acc[3][1]);
            acc[3][2] = fma2(p, b2, acc[3][2]); acc[3][3] = fma2(p, b3, acc[3][3]);
        }
    }

    float a1r[8], a2r[8];
#pragma unroll
    for (int q = 0; q < 8; ++q) {
        a1r[q] = a1[h * 64 + dg * 8 + q];
        a2r[q] = a2[h * 64 + dg * 8 + q];
    }
#pragma unroll
    for (int r = 0; r < 4; ++r) {
        int gi = row0 + rg * 4 + r;
        float vals[8], vr[8];
#pragma unroll
        for (int q = 0; q < 4; ++q) {
            float2 f = unpack2(acc[r][q]);
            vals[2 * q] = f.x; vals[2 * q + 1] = f.y;
            vr[2 * q]     = __uint_as_float(tf32r(f.x));
            vr[2 * q + 1] = __uint_as_float(tf32r(f.y));
        }
        float4 o0 = make_float4(vr[0], vr[1], vr[2], vr[3]);
        float4 o1 = make_float4(vr[4], vr[5], vr[6], vr[7]);
        ((float4*)g_Wh)[(long long)gi * 128 + h * 16 + dg * 2]     = o0;
        ((float4*)g_Wh)[(long long)gi * 128 + h * 16 + dg * 2 + 1] = o1;
        float s1 = 0.f, s2v = 0.f;
#pragma unroll
        for (int q = 0; q < 8; ++q) { s1 += vals[q] * a1r[q]; s2v += vals[q] * a2r[q]; }
#pragma unroll
        for (int d = 4; d; d >>= 1) {
            s1  += __shfl_down_sync(0xffffffffu, s1,  d, 8);
            s2v += __shfl_down_sync(0xffffffffu, s2v, d, 8);
        }
        if (dg == 0) {
            g_f1[h * NN + gi] = s1 * L2E;
            g_f2[h * NN + gi] = s2v * L2E;
        }
    }
}

// ---------------- kernel 2b: per-head max of f2 ----------------
__global__ __launch_bounds__(256) void f2max_kernel() {
    __shared__ float red[8];
    int h = blockIdx.x;
    float m = -3.4e38f;
    for (int i = threadIdx.x; i < NN; i += 256)
        m = fmaxf(m, g_f2[h * NN + i]);
#pragma unroll
    for (int s = 16; s; s >>= 1)
        m = fmaxf(m, __shfl_xor_sync(0xffffffffu, m, s));
    if ((threadIdx.x & 31) == 0) red[threadIdx.x >> 5] = m;
    __syncthreads();
    if (threadIdx.x < 8) {
        m = red[threadIdx.x];
#pragma unroll
        for (int s = 4; s; s >>= 1)
            m = fmaxf(m, __shfl_xor_sync(0x000000ffu, m, s));
        if (threadIdx.x == 0) g_f2max[h] = m;
    }
}

// ---------------- kernel 2c: transpose Wh -> [h][d][j'], permute f2 --------
__global__ __launch_bounds__(256) void transpose_kernel() {
    __shared__ float sh[64 * 72];
    const int jt = blockIdx.x, h = blockIdx.y, t = threadIdx.x;
    const long long j0 = (long long)jt * 64;
#pragma unroll
    for (int s = 0; s < 4; ++s) {
        int idx = t + s * 256;
        int j = idx >> 4, q = idx & 15;
        float4 v = ((const float4*)g_Wh)[(j0 + j) * 128 + h * 16 + q];
        sh[(q * 4 + 0) * 72 + j] = v.x;
        sh[(q * 4 + 1) * 72 + j] = v.y;
        sh[(q * 4 + 2) * 72 + j] = v.z;
        sh[(q * 4 + 3) * 72 + j] = v.w;
    }
    if (t < 64) {
        int jp = (t & ~7) | ((t & 3) << 1) | ((t >> 2) & 1);
        g_f2P[h * NN + j0 + jp] = g_f2[h * NN + j0 + t];
    }
    __syncthreads();
#pragma unroll
    for (int s = 0; s < 4; ++s) {
        int idx = t + s * 256;
        int d = idx >> 4, c = idx & 15;
        int jj = c * 4;
        float4 v;
        v.x = sh[d * 72 + ((jj & ~7) | (((jj + 0) & 1) << 2) | (((jj + 0) & 7) >> 1))];
        v.y = sh[d * 72 + ((jj & ~7) | (((jj + 1) & 1) << 2) | (((jj + 1) & 7) >> 1))];
        v.z = sh[d * 72 + ((jj & ~7) | (((jj + 2) & 1) << 2) | (((jj + 2) & 7) >> 1))];
        v.w = sh[d * 72 + ((jj & ~7) | (((jj + 3) & 1) << 2) | (((jj + 3) & 7) >> 1))];
        ((float4*)g_WhT)[(((long long)(h * 64 + d)) * NN + j0) / 4 + c] = v;
    }
}

// ---------------- kernel 3: attention (tf32 mma, 32 rows/warp) -------------
// 256 threads, 8 warps x 32 rows = 256 rows/CTA. grid (32, 8) = one full wave.
// Each B fragment (LDS.64) feeds TWO mma (row blocks) -> B crossbar traffic/row halved.
__global__ __launch_bounds__(256, 2) void attn_kernel(float* __restrict__ out) {
    __shared__ __align__(16) float    WhS[2][64 * 72];
    __shared__ __align__(16) float2   f2s[2][32];
    __shared__ __align__(16) unsigned maskS[2][512];

    const int h = blockIdx.y, row0 = blockIdx.x * 256, t = threadIdx.x;
    const int lane = t & 31, warp = t >> 5, gid = lane >> 2, tig = lane & 3;
    const int rbase = warp * 32 + gid;   // rows rbase + {0,8,16,24}

    const float f2m = g_f2max[h];
    float f1m[4], c1[4], l[4];
#pragma unroll
    for (int r = 0; r < 4; ++r) {
        float f1v = g_f1[h * NN + row0 + rbase + r * 8];
        float e = f1v + f2m;
        float m = fmaxf(e, 0.2f * e);
        f1m[r] = f1v - m;
        c1[r]  = fmaf(0.2f, f1v, -m);
        l[r]   = 0.f;
    }

    float acc[2][8][4];
#pragma unroll
    for (int blk = 0; blk < 2; ++blk)
#pragma unroll
        for (int nc = 0; nc < 8; ++nc)
#pragma unroll
            for (int q = 0; q < 4; ++q) acc[blk][nc][q] = 0.f;

    const int sd = t >> 2, sc = t & 3;
#define STAGE(jt, b) do {                                                     \
        long long js = (long long)(jt) * 64;                                  \
        const float* srow = &g_WhT[((long long)(h * 64 + sd)) * NN + js];     \
        _Pragma("unroll")                                                     \
        for (int s = 0; s < 4; ++s) {                                         \
            int c = sc * 4 + s;                                               \
            cp16(&WhS[b][sd * 72 + c * 4], srow + c * 4);                     \
        }                                                                     \
        cp8(&maskS[b][t * 2],                                                 \
            &g_mask[(long long)(row0 + t) * MWORDS + (jt) * 2]);              \
        if (t < 16) cp16(&f2s[b][t * 2], &g_f2P[h * NN + js + t * 4]);        \
    } while (0)

    STAGE(0, 0);
    cp_commit();

    for (int jt = 0; jt < 128; ++jt) {
        const int cur = jt & 1;
        if (jt + 1 < 128) STAGE(jt + 1, cur ^ 1);
        cp_commit();
        cp_wait1();
        __syncthreads();

        unsigned mwa[4], mwb[4];
#pragma unroll
        for (int r = 0; r < 4; ++r) {
            mwa[r] = maskS[cur][(rbase + r * 8) * 2];
            mwb[r] = maskS[cur][(rbase + r * 8) * 2 + 1];
        }
        const float* whb = &WhS[cur][gid * 72 + tig * 2];

#pragma unroll
        for (int kc = 0; kc < 8; ++kc) {
            const float2 f2p = f2s[cur][kc * 4 + tig];
            const int k0 = kc * 8 + tig, b0 = k0 & 31, b1 = (k0 + 4) & 31;
            unsigned a[2][4];
#pragma unroll
            for (int blk = 0; blk < 2; ++blk) {
                const int ra = blk * 2, rb = blk * 2 + 1;
                float s0 = fmaxf(f1m[ra] + f2p.x, fmaf(0.2f, f2p.x, c1[ra]));
                float s1 = fmaxf(f1m[rb] + f2p.x, fmaf(0.2f, f2p.x, c1[rb]));
                float s2 = fmaxf(f1m[ra] + f2p.y, fmaf(0.2f, f2p.y, c1[ra]));
                float s3 = fmaxf(f1m[rb] + f2p.y, fmaf(0.2f, f2p.y, c1[rb]));
                const unsigned w0 = (kc < 4) ? mwa[ra] : mwb[ra];
                const unsigned w1 = (kc < 4) ? mwa[rb] : mwb[rb];
                if (!((w0 >> b0) & 1u)) s0 = -3.0e38f;
                if (!((w1 >> b0) & 1u)) s1 = -3.0e38f;
                if (!((w0 >> b1) & 1u)) s2 = -3.0e38f;
                if (!((w1 >> b1) & 1u)) s3 = -3.0e38f;
                a[blk][0] = tf32r(ex2f(s0));
                a[blk][1] = tf32r(ex2f(s1));
                a[blk][2] = tf32r(ex2f(s2));
                a[blk][3] = tf32r(ex2f(s3));
                l[ra] += __uint_as_float(a[blk][0]) + __uint_as_float(a[blk][2]);
                l[rb] += __uint_as_float(a[blk][1]) + __uint_as_float(a[blk][3]);
            }
#pragma unroll
            for (int nc = 0; nc < 8; ++nc) {
                const float2 bb = *(const float2*)(whb + nc * 576 + kc * 8);
                const unsigned bb0 = __float_as_uint(bb.x);
                const unsigned bb1 = __float_as_uint(bb.y);
                mma_tf32(acc[0][nc], a[0][0], a[0][1], a[0][2], a[0][3], bb0, bb1);
                mma_tf32(acc[1][nc], a[1][0], a[1][1], a[1][2], a[1][3], bb0, bb1);
            }
        }
        __syncthreads();
    }

    float inv[4];
#pragma unroll
    for (int r = 0; r < 4; ++r) {
        l[r] += __shfl_xor_sync(0xffffffffu, l[r], 1);
        l[r] += __shfl_xor_sync(0xffffffffu, l[r], 2);
        inv[r] = 1.0f / l[r];
    }

#pragma unroll
    for (int blk = 0; blk < 2; ++blk) {
        const long long ga = row0 + rbase + blk * 16;
        const long long gb = ga + 8;
#pragma unroll
        for (int nc = 0; nc < 8; ++nc) {
            const int col = h * 64 + nc * 8 + tig * 2;
            ((float2*)out)[(ga * 512 + col) >> 1] =
                make_float2(acc[blk][nc][0] * inv[blk * 2],
                            acc[blk][nc][1] * inv[blk * 2]);
            ((float2*)out)[(gb * 512 + col) >> 1] =
                make_float2(acc[blk][nc][2] * inv[blk * 2 + 1],
                            acc[blk][nc][3] * inv[blk * 2 + 1]);
        }
    }
}

// ---------------- launch ----------------
extern "C" void kernel_launch(void* const* d_in, const int* in_sizes, int n_in,
                              void* d_out, int out_size) {
    const float* x   = (const float*)d_in[0];
    const int*   adj = (const int*)d_in[1];
    const float* W   = (const float*)d_in[2];
    const float* a1  = (const float*)d_in[3];
    const float* a2  = (const float*)d_in[4];
    float* out = (float*)d_out;

    mask_kernel<<<(NN * MWORDS) / 64, 256>>>(adj);
    gemm_wh_kernel<<<dim3(NN / 128, HEADS), 256>>>(x, W, a1, a2);
    f2max_kernel<<<HEADS, 256>>>();
    transpose_kernel<<<dim3(NN / 64, HEADS), 256>>>();
    attn_kernel<<<dim3(NN / 256, HEADS), 256>>>(out);
}

// round 10
// speedup vs baseline: 1.9247x; 1.6626x over previous
#include <cuda_runtime.h>
#include <cuda_fp16.h>
#include <cstdint>

#define NN 8192
#define DIN 512
#define DOUT 64
#define HEADS 8
#define MWORDS 256
#define L2E 1.44269504088896f
#define ONE2 0x3C003C00u
#define PSCALE 12.0f   // p scaled by 2^12: lifts fp16 operands out of denormal/flush range

typedef unsigned long long ull;

__device__ float    g_Wh[NN * 512];          // [j][h*64+d] fp32
__device__ __half   g_WhH[HEADS * 64 * NN];  // [h][d][j perm16] fp16
__device__ float    g_f1[HEADS * NN];        // * log2e
__device__ float    g_f2[HEADS * NN];        // * log2e
__device__ float2   g_AC[HEADS * NN];        // (A_i, C_i), scaled by 2^12
__device__ float2   g_BD[HEADS * NN];        // (B_j, D_j), j perm16
__device__ float    g_f2max[HEADS];
__device__ unsigned g_mask[NN * MWORDS];

// ---------------- helpers ----------------
__device__ __forceinline__ ull fma2(ull a, ull b, ull c) {
    ull d; asm("fma.rn.f32x2 %0, %1, %2, %3;" : "=l"(d) : "l"(a), "l"(b), "l"(c));
    return d;
}
__device__ __forceinline__ ull mul2(ull a, ull b) {
    ull d; asm("mul.rn.f32x2 %0, %1, %2;" : "=l"(d) : "l"(a), "l"(b));
    return d;
}
__device__ __forceinline__ ull pack2(float x) {
    ull d; asm("mov.b64 %0, {%1, %1};" : "=l"(d) : "f"(x));
    return d;
}
__device__ __forceinline__ ull pack2f(float lo, float hi) {
    ull d; asm("mov.b64 %0, {%1, %2};" : "=l"(d) : "f"(lo), "f"(hi));
    return d;
}
__device__ __forceinline__ float2 unpack2(ull v) {
    float2 f; asm("mov.b64 {%0, %1}, %2;" : "=f"(f.x), "=f"(f.y) : "l"(v));
    return f;
}
__device__ __forceinline__ float ex2f(float x) {
    float r; asm("ex2.approx.f32 %0, %1;" : "=f"(r) : "f"(x));
    return r;
}
// d = {lo: lo, hi: hi} fp16x2
__device__ __forceinline__ unsigned pack16(float hi, float lo) {
    unsigned r;
    asm("cvt.rn.f16x2.f32 %0, %1, %2;" : "=r"(r) : "f"(hi), "f"(lo));
    return r;
}
// p = max(A*B, C*D) from packed (A,C) and (B,D)
__device__ __forceinline__ float maxmul(ull ac, ull bd) {
    float2 f = unpack2(mul2(ac, bd));
    return fmaxf(f.x, f.y);
}
__device__ __forceinline__ void mma_f16(float c[4], unsigned a0, unsigned a1,
                                        unsigned a2, unsigned a3,
                                        unsigned b0, unsigned b1) {
    asm volatile(
        "mma.sync.aligned.m16n8k16.row.col.f32.f16.f16.f32 "
        "{%0,%1,%2,%3}, {%4,%5,%6,%7}, {%8,%9}, {%0,%1,%2,%3};"
        : "+f"(c[0]), "+f"(c[1]), "+f"(c[2]), "+f"(c[3])
        : "r"(a0), "r"(a1), "r"(a2), "r"(a3), "r"(b0), "r"(b1));
}
__device__ __forceinline__ void cp16(void* dst, const void* src) {
    unsigned d = (unsigned)__cvta_generic_to_shared(dst);
    asm volatile("cp.async.cg.shared.global [%0], [%1], 16;" :: "r"(d), "l"(src));
}
__device__ __forceinline__ void cp8(void* dst, const void* src) {
    unsigned d = (unsigned)__cvta_generic_to_shared(dst);
    asm volatile("cp.async.ca.shared.global [%0], [%1], 8;" :: "r"(d), "l"(src));
}
__device__ __forceinline__ void cp_commit() { asm volatile("cp.async.commit_group;"); }
template <int N> __device__ __forceinline__ void cp_wait() {
    asm volatile("cp.async.wait_group %0;" :: "n"(N));
}

// ---------------- kernel 1: adj -> bitmask ----------------
__global__ __launch_bounds__(256) void mask_kernel(const int* __restrict__ adj) {
    const int UN = 8;
    long long w0 = ((long long)blockIdx.x * 8 + (threadIdx.x >> 5)) * UN;
    int lane = threadIdx.x & 31;
    int v[UN];
#pragma unroll
    for (int u = 0; u < UN; ++u) v[u] = adj[(w0 + u) * 32 + lane];
#pragma unroll
    for (int u = 0; u < UN; ++u) {
        unsigned b = __ballot_sync(0xffffffffu, v[u] > 0);
        if (lane == 0) g_mask[w0 + u] = b;
    }
}

// ---------------- kernel 2: Wh = x @ W (+ f1/f2) ----------------
__global__ __launch_bounds__(256, 2) void gemm_wh_kernel(
    const float* __restrict__ x, const float* __restrict__ W,
    const float* __restrict__ a1, const float* __restrict__ a2)
{
    __shared__ float As[16 * 128];
    __shared__ float Bs[16 * 64];
    const int h = blockIdx.y, row0 = blockIdx.x * 128, t = threadIdx.x;
    const int dg = t & 7, rg = t >> 3;
    const float* Wb = W + h * (DIN * DOUT);

    ull acc[4][4];
#pragma unroll
    for (int r = 0; r < 4; ++r)
#pragma unroll
        for (int q = 0; q < 4; ++q) acc[r][q] = 0ull;

    for (int kt = 0; kt < 32; ++kt) {
        __syncthreads();
#pragma unroll
        for (int s2 = 0; s2 < 2; ++s2) {
            int idx = t + s2 * 256;
            int row = idx >> 2, kq = idx & 3;
            float4 v = ((const float4*)x)[(long long)(row0 + row) * 128 + kt * 4 + kq];
            As[(kq * 4 + 0) * 128 + row] = v.x;
            As[(kq * 4 + 1) * 128 + row] = v.y;
            As[(kq * 4 + 2) * 128 + row] = v.z;
            As[(kq * 4 + 3) * 128 + row] = v.w;
        }
        {
            int k = t >> 4, dq = t & 15;
            ((float4*)Bs)[k * 16 + dq] = ((const float4*)Wb)[(kt * 16 + k) * 16 + dq];
        }
        __syncthreads();
#pragma unroll
        for (int k = 0; k < 16; ++k) {
            float4 av = *(const float4*)&As[k * 128 + rg * 4];
            const ull* bp = (const ull*)&Bs[k * 64 + dg * 8];
            ull b0 = bp[0], b1 = bp[1], b2 = bp[2], b3 = bp[3];
            ull p;
            p = pack2(av.x);
            acc[0][0] = fma2(p, b0, acc[0][0]); acc[0][1] = fma2(p, b1, acc[0][1]);
            acc[0][2] = fma2(p, b2, acc[0][2]); acc[0][3] = fma2(p, b3, acc[0][3]);
            p = pack2(av.y);
            acc[1][0] = fma2(p, b0, acc[1][0]); acc[1][1] = fma2(p, b1, acc[1][1]);
            acc[1][2] = fma2(p, b2, acc[1][2]); acc[1][3] = fma2(p, b3, acc[1][3]);
            p = pack2(av.z);
            acc[2][0] = fma2(p, b0, acc[2][0]); acc[2][1] = fma2(p, b1, acc[2][1]);
            acc[2][2] = fma2(p, b2, acc[2][2]); acc[2][3] = fma2(p, b3, acc[2][3]);
            p = pack2(av.w);
            acc[3][0] = fma2(p, b0, acc[3][0]); acc[3][1] = fma2(p, b1, acc[3][1]);
            acc[3][2] = fma2(p, b2, acc[3][2]); acc[3][3] = fma2(p, b3, acc[3][3]);
        }
    }

    float a1r[8], a2r[8];
#pragma unroll
    for (int q = 0; q < 8; ++q) {
        a1r[q] = a1[h * 64 + dg * 8 + q];
        a2r[q] = a2[h * 64 + dg * 8 + q];
    }
#pragma unroll
    for (int r = 0; r < 4; ++r) {
        int gi = row0 + rg * 4 + r;
        float vals[8];
#pragma unroll
        for (int q = 0; q < 4; ++q) {
            float2 f = unpack2(acc[r][q]);
            vals[2 * q] = f.x; vals[2 * q + 1] = f.y;
        }
        float4 o0 = make_float4(vals[0], vals[1], vals[2], vals[3]);
        float4 o1 = make_float4(vals[4], vals[5], vals[6], vals[7]);
        ((float4*)g_Wh)[(long long)gi * 128 + h * 16 + dg * 2]     = o0;
        ((float4*)g_Wh)[(long long)gi * 128 + h * 16 + dg * 2 + 1] = o1;
        float s1 = 0.f, s2v = 0.f;
#pragma unroll
        for (int q = 0; q < 8; ++q) { s1 += vals[q] * a1r[q]; s2v += vals[q] * a2r[q]; }
#pragma unroll
        for (int d = 4; d; d >>= 1) {
            s1  += __shfl_down_sync(0xffffffffu, s1,  d, 8);
            s2v += __shfl_down_sync(0xffffffffu, s2v, d, 8);
        }
        if (dg == 0) {
            g_f1[h * NN + gi] = s1 * L2E;
            g_f2[h * NN + gi] = s2v * L2E;
        }
    }
}

// ---------------- kernel 2b: per-head max of f2 ----------------
__global__ __launch_bounds__(256) void f2max_kernel() {
    __shared__ float red[8];
    int h = blockIdx.x;
    float m = -3.4e38f;
    for (int i = threadIdx.x; i < NN; i += 256)
        m = fmaxf(m, g_f2[h * NN + i]);
#pragma unroll
    for (int s = 16; s; s >>= 1)
        m = fmaxf(m, __shfl_xor_sync(0xffffffffu, m, s));
    if ((threadIdx.x & 31) == 0) red[threadIdx.x >> 5] = m;
    __syncthreads();
    if (threadIdx.x < 8) {
        m = red[threadIdx.x];
#pragma unroll
        for (int s = 4; s; s >>= 1)
            m = fmaxf(m, __shfl_xor_sync(0x000000ffu, m, s));
        if (threadIdx.x == 0) g_f2max[h] = m;
    }
}

// ---------------- kernel 2c: precompute A,C (rows, 2^12-scaled), B,D (cols) -
// perm16: j lowbits u -> pos 4*((u&7)>>1) + ((u>>3)&1)*2 + (u&1)
__global__ __launch_bounds__(256) void prep_kernel() {
    int h = blockIdx.y;
    int i = blockIdx.x * 256 + threadIdx.x;
    float f2m = g_f2max[h];
    float f1 = g_f1[h * NN + i];
    float e = f1 + f2m;
    float m = fmaxf(e, 0.2f * e);
    g_AC[h * NN + i] =
        make_float2(ex2f(e - m + PSCALE), ex2f(0.2f * e - m + PSCALE));
    float dd = g_f2[h * NN + i] - f2m;
    int u = i & 15;
    int pos = ((u & 7) >> 1) * 4 + ((u >> 3) & 1) * 2 + (u & 1);
    g_BD[h * NN + (i & ~15) + pos] = make_float2(ex2f(dd), ex2f(0.2f * dd));
}

// ---------------- kernel 2d: Wh -> fp16 [h][d][j perm16] --------------------
__global__ __launch_bounds__(256) void whh_kernel() {
    __shared__ float sh[64 * 72];
    const int jt = blockIdx.x, h = blockIdx.y, t = threadIdx.x;
    const long long j0 = (long long)jt * 64;
#pragma unroll
    for (int s = 0; s < 4; ++s) {
        int idx = t + s * 256;
        int j = idx >> 4, q = idx & 15;
        float4 v = ((const float4*)g_Wh)[(j0 + j) * 128 + h * 16 + q];
        sh[(q * 4 + 0) * 72 + j] = v.x;
        sh[(q * 4 + 1) * 72 + j] = v.y;
        sh[(q * 4 + 2) * 72 + j] = v.z;
        sh[(q * 4 + 3) * 72 + j] = v.w;
    }
    __syncthreads();
#pragma unroll
    for (int s = 0; s < 2; ++s) {
        int id = t + s * 256;          // 0..511
        int d = id >> 3, c8 = id & 7;  // 8 f16 per thread-iter
        __half hbuf[8];
#pragma unroll
        for (int e = 0; e < 8; ++e) {
            int p = c8 * 8 + e;
            int pl = p & 15;
            int u = ((pl >> 2) & 3) * 2 + ((pl >> 1) & 1) * 8 + (pl & 1);
            int j = (p & ~15) + u;
            hbuf[e] = __float2half_rn(sh[d * 72 + j]);
        }
        *(uint4*)&g_WhH[((long long)(h * 64 + d)) * NN + j0 + c8 * 8] =
            *(uint4*)hbuf;
    }
}

// ---------------- kernel 3: attention (fp16 k16 mma, no exp in loop) --------
// 256 threads, 8 warps x 32 rows; grid (32, 8) = one wave.
// p_ij = max(A_i*B_j, C_i*D_j) * 2^12; l via ones-column mma (exact consistency).
__global__ __launch_bounds__(256, 2) void attn_kernel(float* __restrict__ out) {
    __shared__ __align__(16) __half   WhS[3][64 * 72];   // stride 72 halfs = 144B
    __shared__ __align__(16) float2   bdS[3][64];
    __shared__ __align__(16) unsigned maskS[3][512];

    const int h = blockIdx.y, row0 = blockIdx.x * 256, t = threadIdx.x;
    const int lane = t & 31, warp = t >> 5, gid = lane >> 2, tig = lane & 3;
    const int rbase = warp * 32 + gid;   // rows rbase + {0,8,16,24}

    ull ACp[4];
#pragma unroll
    for (int r = 0; r < 4; ++r) {
        float2 ac = g_AC[h * NN + row0 + rbase + r * 8];
        ACp[r] = pack2f(ac.x, ac.y);
    }

    float acc[2][8][4];
    float accL[2][4];
#pragma unroll
    for (int b = 0; b < 2; ++b) {
#pragma unroll
        for (int nc = 0; nc < 8; ++nc)
#pragma unroll
            for (int q = 0; q < 4; ++q) acc[b][nc][q] = 0.f;
#pragma unroll
        for (int q = 0; q < 4; ++q) accL[b][q] = 0.f;
    }

    const int sd = t >> 2, sc = t & 3;   // WhS: row sd, chunk pair sc
#define STAGE(jt, b) do {                                                     \
        long long js = (long long)(jt) * 64;                                  \
        const __half* srow = &g_WhH[((long long)(h * 64 + sd)) * NN + js];    \
        cp16(&WhS[b][sd * 72 + sc * 16],     srow + sc * 16);                 \
        cp16(&WhS[b][sd * 72 + sc * 16 + 8], srow + sc * 16 + 8);             \
        cp8(&maskS[b][t * 2],                                                 \
            &g_mask[(long long)(row0 + t) * MWORDS + (jt) * 2]);              \
        if (t < 32) cp16(&bdS[b][t * 2], &g_BD[h * NN + js + t * 2]);         \
    } while (0)

    STAGE(0, 0); cp_commit();
    STAGE(1, 1); cp_commit();

    int cur = 0;
    for (int jt = 0; jt < 128; ++jt) {
        cp_wait<1>();
        __syncthreads();

        unsigned mw0[4], mw1[4];
#pragma unroll
        for (int r = 0; r < 4; ++r) {
            mw0[r] = maskS[cur][(rbase + r * 8) * 2];
            mw1[r] = maskS[cur][(rbase + r * 8) * 2 + 1];
        }
        const __half* whb = &WhS[cur][gid * 72 + tig * 4];
        const float2* bdb = &bdS[cur][tig * 4];

#pragma unroll
        for (int ks = 0; ks < 4; ++ks) {
            const ulonglong2 bdv = *(const ulonglong2*)(bdb + ks * 16);
            const ulonglong2 bdw = *(const ulonglong2*)(bdb + ks * 16 + 2);
            const int sh = ((ks & 1) << 4) + 2 * tig;
            unsigned fa[4][2];
#pragma unroll
            for (int r = 0; r < 4; ++r) {
                const unsigned x = ((ks < 2) ? mw0[r] : mw1[r]) >> sh;
                float p0 = maxmul(ACp[r], bdv.x);
                float p1 = maxmul(ACp[r], bdv.y);
                float p2 = maxmul(ACp[r], bdw.x);
                float p3 = maxmul(ACp[r], bdw.y);
                if (!(x & 1u))     p0 = 0.f;
                if (!(x & 2u))     p1 = 0.f;
                if (!(x & 0x100u)) p2 = 0.f;
                if (!(x & 0x200u)) p3 = 0.f;
                fa[r][0] = pack16(p1, p0);
                fa[r][1] = pack16(p3, p2);
            }
#pragma unroll
            for (int nc = 0; nc < 8; ++nc) {
                const uint2 bb = *(const uint2*)(whb + nc * 576 + ks * 16);
                mma_f16(acc[0][nc], fa[0][0], fa[1][0], fa[0][1], fa[1][1],
                        bb.x, bb.y);
                mma_f16(acc[1][nc], fa[2][0], fa[3][0], fa[2][1], fa[3][1],
                        bb.x, bb.y);
            }
            mma_f16(accL[0], fa[0][0], fa[1][0], fa[0][1], fa[1][1], ONE2, ONE2);
            mma_f16(accL[1], fa[2][0], fa[3][0], fa[2][1], fa[3][1], ONE2, ONE2);
        }

        if (jt < 126) {
            int nb = cur >= 1 ? cur - 1 : cur + 2;   // (jt+2)%3
            STAGE(jt + 2, nb);
        }
        cp_commit();
        cur = (cur == 2) ? 0 : cur + 1;
    }

#pragma unroll
    for (int b = 0; b < 2; ++b) {
        const float invLo = 1.0f / accL[b][0];
        const float invHi = 1.0f / accL[b][2];
        const long long ga = row0 + rbase + b * 16;
        const long long gb = ga + 8;
#pragma unroll
        for (int nc = 0; nc < 8; ++nc) {
            const int col = h * 64 + nc * 8 + tig * 2;
            ((float2*)out)[(ga * 512 + col) >> 1] =
                make_float2(acc[b][nc][0] * invLo, acc[b][nc][1] * invLo);
            ((float2*)out)[(gb * 512 + col) >> 1] =
                make_float2(acc[b][nc][2] * invHi, acc[b][nc][3] * invHi);
        }
    }
}

// ---------------- launch ----------------
extern "C" void kernel_launch(void* const* d_in, const int* in_sizes, int n_in,
                              void* d_out, int out_size) {
    const float* x   = (const float*)d_in[0];
    const int*   adj = (const int*)d_in[1];
    const float* W   = (const float*)d_in[2];
    const float* a1  = (const float*)d_in[3];
    const float* a2  = (const float*)d_in[4];
    float* out = (float*)d_out;

    mask_kernel<<<(NN * MWORDS) / 64, 256>>>(adj);
    gemm_wh_kernel<<<dim3(NN / 128, HEADS), 256>>>(x, W, a1, a2);
    f2max_kernel<<<HEADS, 256>>>();
    prep_kernel<<<dim3(NN / 256, HEADS), 256>>>();
    whh_kernel<<<dim3(NN / 64, HEADS), 256>>>();
    attn_kernel<<<dim3(NN / 256, HEADS), 256>>>(out);
}

// round 11
// speedup vs baseline: 2.3633x; 1.2278x over previous
#include <cuda_runtime.h>
#include <cuda_fp16.h>
#include <cstdint>

#define NN 8192
#define DIN 512
#define DOUT 64
#define HEADS 8
#define MWORDS 256
#define L2E 1.44269504088896f
#define ONE2 0x3C003C00u
#define PSCALE 12.0f   // p scaled by 2^12: lifts fp16 operands out of denormal range

typedef unsigned long long ull;

__device__ __half   g_WhH[HEADS * 64 * NN];  // [h][d][j perm16] fp16
__device__ float    g_xr[NN * DIN];          // tf32-rounded x
__device__ float    g_Wr[HEADS * DIN * DOUT];// tf32-rounded W
__device__ float2   g_w12[HEADS * DIN];      // (W@a1, W@a2)[h][k]
__device__ float    g_f1[HEADS * NN];        // * log2e (exact fp32 path)
__device__ float    g_f2[HEADS * NN];        // * log2e
__device__ float2   g_AC[HEADS * NN];        // (A_i, C_i), scaled by 2^12
__device__ float2   g_BD[HEADS * NN];        // (B_j, D_j), j perm16
__device__ float    g_f2max[HEADS];
__device__ unsigned g_mask[NN * MWORDS];

// ---------------- helpers ----------------
__device__ __forceinline__ ull mul2(ull a, ull b) {
    ull d; asm("mul.rn.f32x2 %0, %1, %2;" : "=l"(d) : "l"(a), "l"(b));
    return d;
}
__device__ __forceinline__ ull pack2f(float lo, float hi) {
    ull d; asm("mov.b64 %0, {%1, %2};" : "=l"(d) : "f"(lo), "f"(hi));
    return d;
}
__device__ __forceinline__ float2 unpack2(ull v) {
    float2 f; asm("mov.b64 {%0, %1}, %2;" : "=f"(f.x), "=f"(f.y) : "l"(v));
    return f;
}
__device__ __forceinline__ unsigned tf32r(float x) {
    unsigned r; asm("cvt.rna.tf32.f32 %0, %1;" : "=r"(r) : "f"(x));
    return r;
}
__device__ __forceinline__ float ex2f(float x) {
    float r; asm("ex2.approx.f32 %0, %1;" : "=f"(r) : "f"(x));
    return r;
}
__device__ __forceinline__ unsigned pack16(float hi, float lo) {
    unsigned r;
    asm("cvt.rn.f16x2.f32 %0, %1, %2;" : "=r"(r) : "f"(hi), "f"(lo));
    return r;
}
__device__ __forceinline__ float maxmul(ull ac, ull bd) {
    float2 f = unpack2(mul2(ac, bd));
    return fmaxf(f.x, f.y);
}
__device__ __forceinline__ void mma_f16(float c[4], unsigned a0, unsigned a1,
                                        unsigned a2, unsigned a3,
                                        unsigned b0, unsigned b1) {
    asm volatile(
        "mma.sync.aligned.m16n8k16.row.col.f32.f16.f16.f32 "
        "{%0,%1,%2,%3}, {%4,%5,%6,%7}, {%8,%9}, {%0,%1,%2,%3};"
        : "+f"(c[0]), "+f"(c[1]), "+f"(c[2]), "+f"(c[3])
        : "r"(a0), "r"(a1), "r"(a2), "r"(a3), "r"(b0), "r"(b1));
}
__device__ __forceinline__ void mma_tf32(float c[4], unsigned a0, unsigned a1,
                                         unsigned a2, unsigned a3,
                                         unsigned b0, unsigned b1) {
    asm volatile(
        "mma.sync.aligned.m16n8k8.row.col.f32.tf32.tf32.f32 "
        "{%0,%1,%2,%3}, {%4,%5,%6,%7}, {%8,%9}, {%0,%1,%2,%3};"
        : "+f"(c[0]), "+f"(c[1]), "+f"(c[2]), "+f"(c[3])
        : "r"(a0), "r"(a1), "r"(a2), "r"(a3), "r"(b0), "r"(b1));
}
__device__ __forceinline__ void cp16(void* dst, const void* src) {
    unsigned d = (unsigned)__cvta_generic_to_shared(dst);
    asm volatile("cp.async.cg.shared.global [%0], [%1], 16;" :: "r"(d), "l"(src));
}
__device__ __forceinline__ void cp8(void* dst, const void* src) {
    unsigned d = (unsigned)__cvta_generic_to_shared(dst);
    asm volatile("cp.async.ca.shared.global [%0], [%1], 8;" :: "r"(d), "l"(src));
}
__device__ __forceinline__ void cp_commit() { asm volatile("cp.async.commit_group;"); }
template <int N> __device__ __forceinline__ void cp_wait() {
    asm volatile("cp.async.wait_group %0;" :: "n"(N));
}

// ---------------- kernel 1: adj -> bitmask ----------------
__global__ __launch_bounds__(256) void mask_kernel(const int* __restrict__ adj) {
    const int UN = 8;
    long long w0 = ((long long)blockIdx.x * 8 + (threadIdx.x >> 5)) * UN;
    int lane = threadIdx.x & 31;
    int v[UN];
#pragma unroll
    for (int u = 0; u < UN; ++u) v[u] = adj[(w0 + u) * 32 + lane];
#pragma unroll
    for (int u = 0; u < UN; ++u) {
        unsigned b = __ballot_sync(0xffffffffu, v[u] > 0);
        if (lane == 0) g_mask[w0 + u] = b;
    }
}

// ---------------- kernel 1b: tf32-round x, W (unbiased rna) -----------------
__global__ __launch_bounds__(256) void round_kernel(const float* __restrict__ x,
                                                    const float* __restrict__ W) {
    int i = blockIdx.x * 256 + threadIdx.x;   // 1,114,112 float4s total
    float4 v;
    float4* dst;
    if (i < 1048576) { v = ((const float4*)x)[i]; dst = &((float4*)g_xr)[i]; }
    else { v = ((const float4*)W)[i - 1048576]; dst = &((float4*)g_Wr)[i - 1048576]; }
    v.x = __uint_as_float(tf32r(v.x));
    v.y = __uint_as_float(tf32r(v.y));
    v.z = __uint_as_float(tf32r(v.z));
    v.w = __uint_as_float(tf32r(v.w));
    *dst = v;
}

// ---------------- kernel 2: Wh GEMM via tf32 mma, fused fp16/perm16 epilogue
// C'[d][j] = W[h]^T (64x512) @ x^T (512x128) per CTA. grid (64, 8), 256 thr.
// warp w: m-block (w&3) (d = (w&3)*16 + gid, +8), n-half (w>>2) (j = nh*64 + nc*8 ...).
#define XSTR 20
#define WSTR 72
__global__ __launch_bounds__(256, 2) void gemm_wh2_kernel() {
    __shared__ __align__(16) float buf[2 * 128 * XSTR + 2 * 16 * WSTR]; // 29,696B
    float* xS = buf;                    // [2][128][20]
    float* wS = buf + 2 * 128 * XSTR;   // [2][16][72]
    __half* Csh = (__half*)buf;         // epilogue overlay [64][136]

    const int h = blockIdx.y, row0 = blockIdx.x * 128, t = threadIdx.x;
    const int lane = t & 31, warp = t >> 5, gid = lane >> 2, tig = lane & 3;
    const int mbase = (warp & 3) * 16, nbase = (warp >> 2) * 64;

    float acc[8][4];
#pragma unroll
    for (int nc = 0; nc < 8; ++nc)
#pragma unroll
        for (int q = 0; q < 4; ++q) acc[nc][q] = 0.f;

    const int sj = t >> 1, sk8 = (t & 1) * 8;     // x staging: j, k-offset
    const int wk = t >> 4, wd = (t & 15) * 4;     // w staging
#define GSTAGE(it, b) do {                                                    \
        const float* xsrc = &g_xr[(long long)(row0 + sj) * 512 + (it) * 16];  \
        cp16(&xS[(b) * 2560 + sj * XSTR + sk8],     xsrc + sk8);              \
        cp16(&xS[(b) * 2560 + sj * XSTR + sk8 + 4], xsrc + sk8 + 4);          \
        cp16(&wS[(b) * 1152 + wk * WSTR + wd],                                \
             &g_Wr[h * (DIN * DOUT) + ((it) * 16 + wk) * 64 + wd]);           \
    } while (0)

    GSTAGE(0, 0); cp_commit();

    for (int it = 0; it < 32; ++it) {
        const int cur = it & 1;
        cp_wait<0>();
        __syncthreads();
        if (it + 1 < 32) GSTAGE(it + 1, cur ^ 1);
        cp_commit();
        const float* xb = xS + cur * 2560;
        const float* wb = wS + cur * 1152;
#pragma unroll
        for (int k8 = 0; k8 < 2; ++k8) {
            const int k0 = k8 * 8;
            const unsigned a0 = __float_as_uint(wb[(k0 + tig) * WSTR + mbase + gid]);
            const unsigned a1 = __float_as_uint(wb[(k0 + tig) * WSTR + mbase + gid + 8]);
            const unsigned a2 = __float_as_uint(wb[(k0 + tig + 4) * WSTR + mbase + gid]);
            const unsigned a3 = __float_as_uint(wb[(k0 + tig + 4) * WSTR + mbase + gid + 8]);
#pragma unroll
            for (int nc = 0; nc < 8; ++nc) {
                const int j = nbase + nc * 8 + gid;
                const unsigned b0 = __float_as_uint(xb[j * XSTR + k0 + tig]);
                const unsigned b1 = __float_as_uint(xb[j * XSTR + k0 + tig + 4]);
                mma_tf32(acc[nc], a0, a1, a2, a3, b0, b1);
            }
        }
    }
    __syncthreads();

    // stage C' as fp16 [d][j] (stride 136)
#pragma unroll
    for (int nc = 0; nc < 8; ++nc) {
        const int j = nbase + nc * 8 + tig * 2;
        *(__half2*)&Csh[(mbase + gid) * 136 + j] =
            __floats2half2_rn(acc[nc][0], acc[nc][1]);
        *(__half2*)&Csh[(mbase + gid + 8) * 136 + j] =
            __floats2half2_rn(acc[nc][2], acc[nc][3]);
    }
    __syncthreads();

    // perm16 gather -> g_WhH (same perm as r10 whh_kernel)
#pragma unroll
    for (int s = 0; s < 4; ++s) {
        int id = t + s * 256;          // 0..1023
        int d = id >> 4, c8 = id & 15;
        __half hbuf[8];
#pragma unroll
        for (int e = 0; e < 8; ++e) {
            int p = c8 * 8 + e;
            int pl = p & 15;
            int u = ((pl >> 2) & 3) * 2 + ((pl >> 1) & 1) * 8 + (pl & 1);
            hbuf[e] = Csh[d * 136 + (p & ~15) + u];
        }
        *(uint4*)&g_WhH[((long long)(h * 64 + d)) * NN + row0 + c8 * 8] =
            *(uint4*)hbuf;
    }
}

// ---------------- kernel 2b: w12 = (W@a1, W@a2) per head, fp32 --------------
__global__ __launch_bounds__(256) void w12_kernel(const float* __restrict__ W,
                                                  const float* __restrict__ a1,
                                                  const float* __restrict__ a2) {
    __shared__ float a1s[64], a2s[64];
    const int h = blockIdx.x, t = threadIdx.x;
    if (t < 64) { a1s[t] = a1[h * 64 + t]; a2s[t] = a2[h * 64 + t]; }
    __syncthreads();
    for (int k = t; k < 512; k += 256) {
        const float* wrow = W + h * (DIN * DOUT) + k * 64;
        float s1 = 0.f, s2 = 0.f;
#pragma unroll 16
        for (int d = 0; d < 64; ++d) {
            float w = wrow[d];
            s1 = fmaf(w, a1s[d], s1);
            s2 = fmaf(w, a2s[d], s2);
        }
        g_w12[h * 512 + k] = make_float2(s1, s2);
    }
}

// ---------------- kernel 2c: f1/f2 = x @ w12 (exact fp32 path) --------------
__global__ __launch_bounds__(256) void f1f2_kernel(const float* __restrict__ x) {
    __shared__ float w1s[8 * 512], w2s[8 * 512];   // 32KB
    const int t = threadIdx.x, lane = t & 31, warp = t >> 5;
    for (int i = t; i < 8 * 512; i += 256) {
        float2 v = g_w12[i];
        w1s[i] = v.x; w2s[i] = v.y;
    }
    __syncthreads();
    for (int it = 0; it < 4; ++it) {
        const int node = blockIdx.x * 32 + warp * 4 + it;
        float4 xv[4];
#pragma unroll
        for (int q = 0; q < 4; ++q)
            xv[q] = ((const float4*)x)[(long long)node * 128 + lane + 32 * q];
        float f1r[8], f2r[8];
#pragma unroll
        for (int h = 0; h < 8; ++h) {
            float s1 = 0.f, s2 = 0.f;
#pragma unroll
            for (int q = 0; q < 4; ++q) {
                float4 w1 = *(const float4*)&w1s[h * 512 + 4 * lane + 128 * q];
                float4 w2 = *(const float4*)&w2s[h * 512 + 4 * lane + 128 * q];
                s1 = fmaf(xv[q].x, w1.x, s1); s1 = fmaf(xv[q].y, w1.y, s1);
                s1 = fmaf(xv[q].z, w1.z, s1); s1 = fmaf(xv[q].w, w1.w, s1);
                s2 = fmaf(xv[q].x, w2.x, s2); s2 = fmaf(xv[q].y, w2.y, s2);
                s2 = fmaf(xv[q].z, w2.z, s2); s2 = fmaf(xv[q].w, w2.w, s2);
            }
            f1r[h] = s1; f2r[h] = s2;
        }
#pragma unroll
        for (int s = 16; s; s >>= 1)
#pragma unroll
            for (int h = 0; h < 8; ++h) {
                f1r[h] += __shfl_xor_sync(0xffffffffu, f1r[h], s);
                f2r[h] += __shfl_xor_sync(0xffffffffu, f2r[h], s);
            }
        if (lane == 0)
#pragma unroll
            for (int h = 0; h < 8; ++h) {
                g_f1[h * NN + node] = f1r[h] * L2E;
                g_f2[h * NN + node] = f2r[h] * L2E;
            }
    }
}

// ---------------- kernel 2d: per-head max of f2 ----------------
__global__ __launch_bounds__(256) void f2max_kernel() {
    __shared__ float red[8];
    int h = blockIdx.x;
    float m = -3.4e38f;
    for (int i = threadIdx.x; i < NN; i += 256)
        m = fmaxf(m, g_f2[h * NN + i]);
#pragma unroll
    for (int s = 16; s; s >>= 1)
        m = fmaxf(m, __shfl_xor_sync(0xffffffffu, m, s));
    if ((threadIdx.x & 31) == 0) red[threadIdx.x >> 5] = m;
    __syncthreads();
    if (threadIdx.x < 8) {
        m = red[threadIdx.x];
#pragma unroll
        for (int s = 4; s; s >>= 1)
            m = fmaxf(m, __shfl_xor_sync(0x000000ffu, m, s));
        if (threadIdx.x == 0) g_f2max[h] = m;
    }
}

// ---------------- kernel 2e: precompute A,C (2^12-scaled) and B,D (perm16) --
__global__ __launch_bounds__(256) void prep_kernel() {
    int h = blockIdx.y;
    int i = blockIdx.x * 256 + threadIdx.x;
    float f2m = g_f2max[h];
    float f1 = g_f1[h * NN + i];
    float e = f1 + f2m;
    float m = fmaxf(e, 0.2f * e);
    g_AC[h * NN + i] =
        make_float2(ex2f(e - m + PSCALE), ex2f(0.2f * e - m + PSCALE));
    float dd = g_f2[h * NN + i] - f2m;
    int u = i & 15;
    int pos = ((u & 7) >> 1) * 4 + ((u >> 3) & 1) * 2 + (u & 1);
    g_BD[h * NN + (i & ~15) + pos] = make_float2(ex2f(dd), ex2f(0.2f * dd));
}

// ---------------- kernel 3: attention (fp16 k16 mma, no exp in loop) --------
__global__ __launch_bounds__(256, 2) void attn_kernel(float* __restrict__ out) {
    __shared__ __align__(16) __half   WhS[3][64 * 72];
    __shared__ __align__(16) float2   bdS[3][64];
    __shared__ __align__(16) unsigned maskS[3][512];

    const int h = blockIdx.y, row0 = blockIdx.x * 256, t = threadIdx.x;
    const int lane = t & 31, warp = t >> 5, gid = lane >> 2, tig = lane & 3;
    const int rbase = warp * 32 + gid;

    ull ACp[4];
#pragma unroll
    for (int r = 0; r < 4; ++r) {
        float2 ac = g_AC[h * NN + row0 + rbase + r * 8];
        ACp[r] = pack2f(ac.x, ac.y);
    }

    float acc[2][8][4];
    float accL[2][4];
#pragma unroll
    for (int b = 0; b < 2; ++b) {
#pragma unroll
        for (int nc = 0; nc < 8; ++nc)
#pragma unroll
            for (int q = 0; q < 4; ++q) acc[b][nc][q] = 0.f;
#pragma unroll
        for (int q = 0; q < 4; ++q) accL[b][q] = 0.f;
    }

    const int sd = t >> 2, sc = t & 3;
#define STAGE(jt, b) do {                                                     \
        long long js = (long long)(jt) * 64;                                  \
        const __half* srow = &g_WhH[((long long)(h * 64 + sd)) * NN + js];    \
        cp16(&WhS[b][sd * 72 + sc * 16],     srow + sc * 16);                 \
        cp16(&WhS[b][sd * 72 + sc * 16 + 8], srow + sc * 16 + 8);             \
        cp8(&maskS[b][t * 2],                                                 \
            &g_mask[(long long)(row0 + t) * MWORDS + (jt) * 2]);              \
        if (t < 32) cp16(&bdS[b][t * 2], &g_BD[h * NN + js + t * 2]);         \
    } while (0)

    STAGE(0, 0); cp_commit();
    STAGE(1, 1); cp_commit();

    int cur = 0;
    for (int jt = 0; jt < 128; ++jt) {
        cp_wait<1>();
        __syncthreads();

        unsigned mw0[4], mw1[4];
#pragma unroll
        for (int r = 0; r < 4; ++r) {
            mw0[r] = maskS[cur][(rbase + r * 8) * 2];
            mw1[r] = maskS[cur][(rbase + r * 8) * 2 + 1];
        }
        const __half* whb = &WhS[cur][gid * 72 + tig * 4];
        const float2* bdb = &bdS[cur][tig * 4];

#pragma unroll
        for (int ks = 0; ks < 4; ++ks) {
            const ulonglong2 bdv = *(const ulonglong2*)(bdb + ks * 16);
            const ulonglong2 bdw = *(const ulonglong2*)(bdb + ks * 16 + 2);
            const int sh = ((ks & 1) << 4) + 2 * tig;
            unsigned fa[4][2];
#pragma unroll
            for (int r = 0; r < 4; ++r) {
                const unsigned x = ((ks < 2) ? mw0[r] : mw1[r]) >> sh;
                float p0 = maxmul(ACp[r], bdv.x);
                float p1 = maxmul(ACp[r], bdv.y);
                float p2 = maxmul(ACp[r], bdw.x);
                float p3 = maxmul(ACp[r], bdw.y);
                if (!(x & 1u))     p0 = 0.f;
                if (!(x & 2u))     p1 = 0.f;
                if (!(x & 0x100u)) p2 = 0.f;
                if (!(x & 0x200u)) p3 = 0.f;
                fa[r][0] = pack16(p1, p0);
                fa[r][1] = pack16(p3, p2);
            }
#pragma unroll
            for (int nc = 0; nc < 8; ++nc) {
                const uint2 bb = *(const uint2*)(whb + nc * 576 + ks * 16);
                mma_f16(acc[0][nc], fa[0][0], fa[1][0], fa[0][1], fa[1][1],
                        bb.x, bb.y);
                mma_f16(acc[1][nc], fa[2][0], fa[3][0], fa[2][1], fa[3][1],
                        bb.x, bb.y);
            }
            mma_f16(accL[0], fa[0][0], fa[1][0], fa[0][1], fa[1][1], ONE2, ONE2);
            mma_f16(accL[1], fa[2][0], fa[3][0], fa[2][1], fa[3][1], ONE2, ONE2);
        }

        if (jt < 126) {
            int nb = cur >= 1 ? cur - 1 : cur + 2;   // (jt+2)%3
            STAGE(jt + 2, nb);
        }
        cp_commit();
        cur = (cur == 2) ? 0 : cur + 1;
    }

#pragma unroll
    for (int b = 0; b < 2; ++b) {
        const float invLo = 1.0f / accL[b][0];
        const float invHi = 1.0f / accL[b][2];
        const long long ga = row0 + rbase + b * 16;
        const long long gb = ga + 8;
#pragma unroll
        for (int nc = 0; nc < 8; ++nc) {
            const int col = h * 64 + nc * 8 + tig * 2;
            ((float2*)out)[(ga * 512 + col) >> 1] =
                make_float2(acc[b][nc][0] * invLo, acc[b][nc][1] * invLo);
            ((float2*)out)[(gb * 512 + col) >> 1] =
                make_float2(acc[b][nc][2] * invHi, acc[b][nc][3] * invHi);
        }
    }
}

// ---------------- launch ----------------
extern "C" void kernel_launch(void* const* d_in, const int* in_sizes, int n_in,
                              void* d_out, int out_size) {
    const float* x   = (const float*)d_in[0];
    const int*   adj = (const int*)d_in[1];
    const float* W   = (const float*)d_in[2];
    const float* a1  = (const float*)d_in[3];
    const float* a2  = (const float*)d_in[4];
    float* out = (float*)d_out;

    mask_kernel<<<(NN * MWORDS) / 64, 256>>>(adj);
    round_kernel<<<(1048576 + 65536) / 256, 256>>>(x, W);
    gemm_wh2_kernel<<<dim3(NN / 128, HEADS), 256>>>();
    w12_kernel<<<HEADS, 256>>>(W, a1, a2);
    f1f2_kernel<<<NN / 32, 256>>>(x);
    f2max_kernel<<<HEADS, 256>>>();
    prep_kernel<<<dim3(NN / 256, HEADS), 256>>>();
    attn_kernel<<<dim3(NN / 256, HEADS), 256>>>(out);
}